// round 4
// baseline (speedup 1.0000x reference)
#include <cuda_runtime.h>

#define NN 100000
#define F1 128      // HEADS*HID
#define HEADS 4
#define OC 32
#define NEG 0.2f

// ---------------- scratch (static device globals; no allocation) ----------------
__device__ __align__(16) float g_h1[NN * F1];      // layer1 linear output
__device__ __align__(16) float g_out1[NN * F1];    // layer1 aggregated output (ELU'd in place)
__device__ __align__(16) float g_as1[NN * HEADS];
__device__ __align__(16) float g_ad1[NN * HEADS];
__device__ __align__(16) float g_den1[NN * HEADS]; // denom, then inverse in place
__device__ __align__(16) float g_h2[NN * OC];
__device__ __align__(16) float g_as2[NN];
__device__ __align__(16) float g_ad2[NN];
__device__ __align__(16) float g_den2[NN];
__device__ __align__(16) float g_out2[NN * OC];

__device__ __forceinline__ float lrelu(float x) { return x > 0.f ? x : NEG * x; }

__device__ __forceinline__ void red_v4(float* p, float4 v) {
    asm volatile("red.global.add.v4.f32 [%0], {%1,%2,%3,%4};"
                 :: "l"(p), "f"(v.x), "f"(v.y), "f"(v.z), "f"(v.w) : "memory");
}

// ---------------- zero accumulators ----------------
__global__ void zero_kernel() {
    long long i0 = (long long)blockIdx.x * blockDim.x + threadIdx.x;
    long long stride = (long long)gridDim.x * blockDim.x;
    float4 z = make_float4(0.f, 0.f, 0.f, 0.f);
    for (long long i = i0; i < (long long)NN * F1 / 4; i += stride) ((float4*)g_out1)[i] = z;
    for (long long i = i0; i < (long long)NN * OC / 4; i += stride) ((float4*)g_out2)[i] = z;
    for (long long i = i0; i < (long long)NN * HEADS / 4; i += stride) ((float4*)g_den1)[i] = z;
    for (long long i = i0; i < (long long)NN; i += stride) g_den2[i] = 0.f;
}

// ---------------- GEMM1: h1[N,128] = x[N,128] @ W1[128,128] ----------------
__global__ void gemm1_kernel(const float* __restrict__ x, const float* __restrict__ W, int n) {
    __shared__ float xs[64][68];  // [k][row], padded
    __shared__ float ws[64][64];  // [k][col]
    int tid = threadIdx.x;
    int tx = tid & 15, ty = tid >> 4;
    int row0 = blockIdx.x * 64, col0 = blockIdx.y * 64;
    float acc[4][4] = {};
    for (int kt = 0; kt < 2; kt++) {
        int kb = kt * 64;
        for (int i = tid; i < 4096; i += 256) {
            int r = i >> 6, k = i & 63;
            int gr = row0 + r;
            xs[k][r] = (gr < n) ? x[gr * 128 + kb + k] : 0.f;
        }
        for (int i = tid; i < 4096; i += 256) {
            int k = i >> 6, c = i & 63;
            ws[k][c] = W[(kb + k) * 128 + col0 + c];
        }
        __syncthreads();
#pragma unroll 8
        for (int k = 0; k < 64; k++) {
            float4 a = *(const float4*)&xs[k][ty * 4];
            float4 b = *(const float4*)&ws[k][tx * 4];
            float ar[4] = {a.x, a.y, a.z, a.w};
            float br[4] = {b.x, b.y, b.z, b.w};
#pragma unroll
            for (int ii = 0; ii < 4; ii++)
#pragma unroll
                for (int jj = 0; jj < 4; jj++) acc[ii][jj] += ar[ii] * br[jj];
        }
        __syncthreads();
    }
#pragma unroll
    for (int ii = 0; ii < 4; ii++) {
        int gr = row0 + ty * 4 + ii;
        if (gr < n) {
            float4 v = make_float4(acc[ii][0], acc[ii][1], acc[ii][2], acc[ii][3]);
            *(float4*)&g_h1[gr * 128 + col0 + tx * 4] = v;
        }
    }
}

// ---------------- attention logits layer 1 ----------------
__global__ void att1_kernel(const float4* __restrict__ asr, const float4* __restrict__ adr, int n) {
    int i = blockIdx.x * blockDim.x + threadIdx.x;
    if (i >= n) return;
    const float4* hp = (const float4*)(g_h1 + (long long)i * 128);
#pragma unroll
    for (int h = 0; h < 4; h++) {
        float s = 0.f, d = 0.f;
#pragma unroll
        for (int j = 0; j < 8; j++) {
            float4 v = hp[h * 8 + j];
            float4 a = asr[h * 8 + j];
            float4 b = adr[h * 8 + j];
            s += v.x * a.x + v.y * a.y + v.z * a.z + v.w * a.w;
            d += v.x * b.x + v.y * b.y + v.z * b.z + v.w * b.w;
        }
        g_as1[i * 4 + h] = s;
        g_ad1[i * 4 + h] = d;
    }
}

// ---------------- edge pass 1 (layer1 denominator) ----------------
__global__ void edge1_denom(const int* __restrict__ src, const int* __restrict__ dst, int e) {
    int i = blockIdx.x * blockDim.x + threadIdx.x;
    if (i >= e) return;
    int s = src[i], d = dst[i];
    float4 as = *(const float4*)(g_as1 + s * 4);
    float4 ad = *(const float4*)(g_ad1 + d * 4);
    float4 v;
    v.x = __expf(lrelu(as.x + ad.x));
    v.y = __expf(lrelu(as.y + ad.y));
    v.z = __expf(lrelu(as.z + ad.z));
    v.w = __expf(lrelu(as.w + ad.w));
    red_v4(g_den1 + d * 4, v);
}

// ---------------- per-node: add self-loop, invert denom ----------------
__global__ void node1_inv(int n) {
    int i = blockIdx.x * blockDim.x + threadIdx.x;
    if (i >= n) return;
    float4 as = ((const float4*)g_as1)[i];
    float4 ad = ((const float4*)g_ad1)[i];
    float4 den = ((const float4*)g_den1)[i];
    den.x += __expf(lrelu(as.x + ad.x));
    den.y += __expf(lrelu(as.y + ad.y));
    den.z += __expf(lrelu(as.z + ad.z));
    den.w += __expf(lrelu(as.w + ad.w));
    float4 inv = make_float4(1.f / den.x, 1.f / den.y, 1.f / den.z, 1.f / den.w);
    ((float4*)g_den1)[i] = inv;
}

// ---------------- edge pass 2 (layer1 scatter): one warp per edge ----------------
__global__ void edge1_scatter(const int* __restrict__ src, const int* __restrict__ dst, int e) {
    int g = blockIdx.x * blockDim.x + threadIdx.x;
    int eidx = g >> 5;
    int lane = g & 31;
    if (eidx >= e) return;
    int s = src[eidx], d = dst[eidx];
    int h = lane >> 3;
    float a = lrelu(g_as1[s * 4 + h] + g_ad1[d * 4 + h]);
    float w = __expf(a) * g_den1[d * 4 + h];
    float4 hv = *(const float4*)(g_h1 + (long long)s * 128 + lane * 4);
    float4 m = make_float4(hv.x * w, hv.y * w, hv.z * w, hv.w * w);
    red_v4(g_out1 + (long long)d * 128 + lane * 4, m);
}

// ---------------- finalize layer1: self-loop msg + bias + ELU (in place) ----------------
__global__ void node1_final(const float* __restrict__ b1, int n) {
    int g = blockIdx.x * blockDim.x + threadIdx.x;
    int nid = g >> 5;
    int lane = g & 31;
    if (nid >= n) return;
    int h = lane >> 3;
    float a = lrelu(g_as1[nid * 4 + h] + g_ad1[nid * 4 + h]);
    float w = __expf(a) * g_den1[nid * 4 + h];
    float4 o = *(const float4*)(g_out1 + (long long)nid * 128 + lane * 4);
    float4 hv = *(const float4*)(g_h1 + (long long)nid * 128 + lane * 4);
    float4 bb = *(const float4*)(b1 + lane * 4);
    o.x += hv.x * w + bb.x;
    o.y += hv.y * w + bb.y;
    o.z += hv.z * w + bb.z;
    o.w += hv.w * w + bb.w;
    o.x = o.x > 0.f ? o.x : (__expf(o.x) - 1.f);
    o.y = o.y > 0.f ? o.y : (__expf(o.y) - 1.f);
    o.z = o.z > 0.f ? o.z : (__expf(o.z) - 1.f);
    o.w = o.w > 0.f ? o.w : (__expf(o.w) - 1.f);
    *(float4*)(g_out1 + (long long)nid * 128 + lane * 4) = o;
}

// ---------------- GEMM2: h2[N,32] = out1[N,128] @ W2[128,32] ----------------
__global__ void gemm2_kernel(const float* __restrict__ W, int n) {
    __shared__ float xs[64][68];
    __shared__ float ws[64][32];
    int tid = threadIdx.x;   // 128 threads
    int tx = tid & 7, ty = tid >> 3;
    int row0 = blockIdx.x * 64;
    float acc[4][4] = {};
    for (int kt = 0; kt < 2; kt++) {
        int kb = kt * 64;
        for (int i = tid; i < 4096; i += 128) {
            int r = i >> 6, k = i & 63;
            int gr = row0 + r;
            xs[k][r] = (gr < n) ? g_out1[(long long)gr * 128 + kb + k] : 0.f;
        }
        for (int i = tid; i < 2048; i += 128) {
            int k = i >> 5, c = i & 31;
            ws[k][c] = W[(kb + k) * 32 + c];
        }
        __syncthreads();
#pragma unroll 8
        for (int k = 0; k < 64; k++) {
            float4 a = *(const float4*)&xs[k][ty * 4];
            float4 b = *(const float4*)&ws[k][tx * 4];
            float ar[4] = {a.x, a.y, a.z, a.w};
            float br[4] = {b.x, b.y, b.z, b.w};
#pragma unroll
            for (int ii = 0; ii < 4; ii++)
#pragma unroll
                for (int jj = 0; jj < 4; jj++) acc[ii][jj] += ar[ii] * br[jj];
        }
        __syncthreads();
    }
#pragma unroll
    for (int ii = 0; ii < 4; ii++) {
        int gr = row0 + ty * 4 + ii;
        if (gr < n) {
            float4 v = make_float4(acc[ii][0], acc[ii][1], acc[ii][2], acc[ii][3]);
            *(float4*)&g_h2[gr * 32 + tx * 4] = v;
        }
    }
}

// ---------------- attention logits layer 2 (1 head) ----------------
__global__ void att2_kernel(const float4* __restrict__ asr, const float4* __restrict__ adr, int n) {
    int i = blockIdx.x * blockDim.x + threadIdx.x;
    if (i >= n) return;
    const float4* hp = (const float4*)(g_h2 + i * 32);
    float s = 0.f, d = 0.f;
#pragma unroll
    for (int j = 0; j < 8; j++) {
        float4 v = hp[j];
        float4 a = asr[j];
        float4 b = adr[j];
        s += v.x * a.x + v.y * a.y + v.z * a.z + v.w * a.w;
        d += v.x * b.x + v.y * b.y + v.z * b.z + v.w * b.w;
    }
    g_as2[i] = s;
    g_ad2[i] = d;
}

// ---------------- edge pass 1 (layer2 denominator) ----------------
__global__ void edge2_denom(const int* __restrict__ src, const int* __restrict__ dst, int e) {
    int i = blockIdx.x * blockDim.x + threadIdx.x;
    if (i >= e) return;
    int s = src[i], d = dst[i];
    float v = __expf(lrelu(g_as2[s] + g_ad2[d]));
    atomicAdd(g_den2 + d, v);
}

__global__ void node2_inv(int n) {
    int i = blockIdx.x * blockDim.x + threadIdx.x;
    if (i >= n) return;
    float den = g_den2[i] + __expf(lrelu(g_as2[i] + g_ad2[i]));
    g_den2[i] = 1.f / den;
}

// ---------------- edge pass 2 (layer2 scatter): 8 threads per edge ----------------
__global__ void edge2_scatter(const int* __restrict__ src, const int* __restrict__ dst, int e) {
    int g = blockIdx.x * blockDim.x + threadIdx.x;
    int eidx = g >> 3;
    int r = g & 7;
    if (eidx >= e) return;
    int s = src[eidx], d = dst[eidx];
    float a = lrelu(g_as2[s] + g_ad2[d]);
    float w = __expf(a) * g_den2[d];
    float4 hv = ((const float4*)g_h2)[s * 8 + r];
    float4 m = make_float4(hv.x * w, hv.y * w, hv.z * w, hv.w * w);
    red_v4(g_out2 + d * 32 + r * 4, m);
}

// ---------------- finalize: self-loop + bias + log_softmax ----------------
__global__ void final_out(const float* __restrict__ b2, float* __restrict__ out, int n) {
    int i = blockIdx.x * blockDim.x + threadIdx.x;
    if (i >= n) return;
    float a = lrelu(g_as2[i] + g_ad2[i]);
    float w = __expf(a) * g_den2[i];
    float v[32];
    const float4* o2 = (const float4*)(g_out2 + i * 32);
    const float4* h2 = (const float4*)(g_h2 + i * 32);
#pragma unroll
    for (int j = 0; j < 8; j++) {
        float4 av = o2[j];
        float4 bv = h2[j];
        float4 bb = ((const float4*)b2)[j];
        v[4 * j + 0] = av.x + bv.x * w + bb.x;
        v[4 * j + 1] = av.y + bv.y * w + bb.y;
        v[4 * j + 2] = av.z + bv.z * w + bb.z;
        v[4 * j + 3] = av.w + bv.w * w + bb.w;
    }
    float mx = v[0];
#pragma unroll
    for (int k = 1; k < 32; k++) mx = fmaxf(mx, v[k]);
    float s = 0.f;
#pragma unroll
    for (int k = 0; k < 32; k++) s += __expf(v[k] - mx);
    float lse = mx + logf(s);
#pragma unroll
    for (int j = 0; j < 8; j++) {
        float4 r = make_float4(v[4 * j] - lse, v[4 * j + 1] - lse, v[4 * j + 2] - lse, v[4 * j + 3] - lse);
        ((float4*)(out + (long long)i * 32))[j] = r;
    }
}

extern "C" void kernel_launch(void* const* d_in, const int* in_sizes, int n_in,
                              void* d_out, int out_size) {
    const float* x   = (const float*)d_in[0];
    const int*   ei  = (const int*)d_in[1];   // edge_index materializes as int32 (JAX x64 off)
    const float* W1  = (const float*)d_in[2];
    const float* at_s1 = (const float*)d_in[3];
    const float* at_d1 = (const float*)d_in[4];
    const float* b1  = (const float*)d_in[5];
    const float* W2  = (const float*)d_in[6];
    const float* at_s2 = (const float*)d_in[7];
    const float* at_d2 = (const float*)d_in[8];
    const float* b2  = (const float*)d_in[9];
    float* out = (float*)d_out;

    int n = in_sizes[0] / 128;
    int e = in_sizes[1] / 2;
    const int* src = ei;
    const int* dst = ei + e;

    zero_kernel<<<8192, 256>>>();

    dim3 g1((n + 63) / 64, 2);
    gemm1_kernel<<<g1, 256>>>(x, W1, n);
    att1_kernel<<<(n + 255) / 256, 256>>>((const float4*)at_s1, (const float4*)at_d1, n);

    edge1_denom<<<(e + 255) / 256, 256>>>(src, dst, e);
    node1_inv<<<(n + 255) / 256, 256>>>(n);
    edge1_scatter<<<(int)(((long long)e * 32 + 255) / 256), 256>>>(src, dst, e);
    node1_final<<<(n * 32 + 255) / 256, 256>>>(b1, n);

    gemm2_kernel<<<(n + 63) / 64, 128>>>(W2, n);
    att2_kernel<<<(n + 255) / 256, 256>>>((const float4*)at_s2, (const float4*)at_d2, n);

    edge2_denom<<<(e + 255) / 256, 256>>>(src, dst, e);
    node2_inv<<<(n + 255) / 256, 256>>>(n);
    edge2_scatter<<<(int)(((long long)e * 8 + 255) / 256), 256>>>(src, dst, e);
    final_out<<<(n + 255) / 256, 256>>>(b2, out, n);
}

// round 9
// speedup vs baseline: 1.4442x; 1.4442x over previous
#include <cuda_runtime.h>

#define NN 100000
#define F1 128
#define HEADS 4
#define OC 32
#define NEG 0.2f
#define MAXE 1700000

// ---------------- scratch (static device globals) ----------------
__device__ __align__(16) float g_h1[NN * F1];
__device__ __align__(16) float g_out1[NN * F1];
__device__ __align__(16) float g_as1[NN * HEADS];
__device__ __align__(16) float g_ad1[NN * HEADS];
__device__ __align__(16) float g_h2[NN * OC];
__device__ __align__(16) float g_as2[NN];
__device__ __align__(16) float g_ad2[NN];
__device__ int g_deg[NN];
__device__ int g_off[NN + 1];
__device__ int g_cursor[NN];
__device__ int g_bsum[1024];
__device__ int g_csr[MAXE];

__device__ __forceinline__ float lrelu(float x) { return x > 0.f ? x : NEG * x; }

// ---------------- CSR build ----------------
__global__ void zero_deg(int n) {
    int i = blockIdx.x * blockDim.x + threadIdx.x;
    if (i < n) g_deg[i] = 0;
}

__global__ void hist_kernel(const int* __restrict__ dst, int e) {
    int i = blockIdx.x * blockDim.x + threadIdx.x;
    if (i < e) atomicAdd(&g_deg[dst[i]], 1);
}

// per-block exclusive scan (256 threads)
__global__ void scan_block(int n) {
    __shared__ int sh[2][256];
    int t = threadIdx.x;
    int i = blockIdx.x * 256 + t;
    int val = (i < n) ? g_deg[i] : 0;
    int cur = 0;
    sh[0][t] = val;
    __syncthreads();
#pragma unroll
    for (int o = 1; o < 256; o <<= 1) {
        int v = sh[cur][t];
        if (t >= o) v += sh[cur][t - o];
        sh[cur ^ 1][t] = v;
        cur ^= 1;
        __syncthreads();
    }
    int incl = sh[cur][t];
    if (i < n) g_off[i] = incl - val;       // block-local exclusive
    if (t == 255) g_bsum[blockIdx.x] = incl;
}

__global__ void scan_top(int nb) {
    __shared__ int sh[2][1024];
    int t = threadIdx.x;
    int val = (t < nb) ? g_bsum[t] : 0;
    int cur = 0;
    sh[0][t] = val;
    __syncthreads();
#pragma unroll
    for (int o = 1; o < 1024; o <<= 1) {
        int v = sh[cur][t];
        if (t >= o) v += sh[cur][t - o];
        sh[cur ^ 1][t] = v;
        cur ^= 1;
        __syncthreads();
    }
    if (t < nb) g_bsum[t] = sh[cur][t] - val;  // exclusive
}

__global__ void scan_add(int n, int e) {
    int i = blockIdx.x * blockDim.x + threadIdx.x;
    if (i < n) {
        int off = g_off[i] + g_bsum[i >> 8];
        g_off[i] = off;
        g_cursor[i] = off;
    }
    if (i == 0) g_off[n] = e;
}

__global__ void fill_kernel(const int* __restrict__ src, const int* __restrict__ dst, int e) {
    int i = blockIdx.x * blockDim.x + threadIdx.x;
    if (i >= e) return;
    int pos = atomicAdd(&g_cursor[dst[i]], 1);
    g_csr[pos] = src[i];
}

// ---------------- GEMM1: h1[N,128] = x[N,128] @ W1[128,128] ----------------
__global__ void gemm1_kernel(const float* __restrict__ x, const float* __restrict__ W, int n) {
    __shared__ float xs[64][68];
    __shared__ float ws[64][64];
    int tid = threadIdx.x;
    int tx = tid & 15, ty = tid >> 4;
    int row0 = blockIdx.x * 64, col0 = blockIdx.y * 64;
    float acc[4][4] = {};
    for (int kt = 0; kt < 2; kt++) {
        int kb = kt * 64;
        for (int i = tid; i < 4096; i += 256) {
            int r = i >> 6, k = i & 63;
            int gr = row0 + r;
            xs[k][r] = (gr < n) ? x[gr * 128 + kb + k] : 0.f;
        }
        for (int i = tid; i < 4096; i += 256) {
            int k = i >> 6, c = i & 63;
            ws[k][c] = W[(kb + k) * 128 + col0 + c];
        }
        __syncthreads();
#pragma unroll 8
        for (int k = 0; k < 64; k++) {
            float4 a = *(const float4*)&xs[k][ty * 4];
            float4 b = *(const float4*)&ws[k][tx * 4];
            float ar[4] = {a.x, a.y, a.z, a.w};
            float br[4] = {b.x, b.y, b.z, b.w};
#pragma unroll
            for (int ii = 0; ii < 4; ii++)
#pragma unroll
                for (int jj = 0; jj < 4; jj++) acc[ii][jj] += ar[ii] * br[jj];
        }
        __syncthreads();
    }
#pragma unroll
    for (int ii = 0; ii < 4; ii++) {
        int gr = row0 + ty * 4 + ii;
        if (gr < n) {
            float4 v = make_float4(acc[ii][0], acc[ii][1], acc[ii][2], acc[ii][3]);
            *(float4*)&g_h1[gr * 128 + col0 + tx * 4] = v;
        }
    }
}

// ---------------- attention logits layer 1 ----------------
__global__ void att1_kernel(const float4* __restrict__ asr, const float4* __restrict__ adr, int n) {
    int i = blockIdx.x * blockDim.x + threadIdx.x;
    if (i >= n) return;
    const float4* hp = (const float4*)(g_h1 + (long long)i * 128);
#pragma unroll
    for (int h = 0; h < 4; h++) {
        float s = 0.f, d = 0.f;
#pragma unroll
        for (int j = 0; j < 8; j++) {
            float4 v = hp[h * 8 + j];
            float4 a = asr[h * 8 + j];
            float4 b = adr[h * 8 + j];
            s += v.x * a.x + v.y * a.y + v.z * a.z + v.w * a.w;
            d += v.x * b.x + v.y * b.y + v.z * b.z + v.w * b.w;
        }
        g_as1[i * 4 + h] = s;
        g_ad1[i * 4 + h] = d;
    }
}

// ---------------- layer1 aggregation: one warp per dst node ----------------
__global__ void agg1_kernel(const float* __restrict__ b1, int n) {
    int w = (blockIdx.x * blockDim.x + threadIdx.x) >> 5;
    int lane = threadIdx.x & 31;
    if (w >= n) return;
    int rs = g_off[w], re = g_off[w + 1];
    int h = lane >> 3;
    float4 ad4 = ((const float4*)g_ad1)[w];
    float adh = (h == 0) ? ad4.x : (h == 1) ? ad4.y : (h == 2) ? ad4.z : ad4.w;

    // pass 1: denominators (all 4 heads)
    float4 den = make_float4(0.f, 0.f, 0.f, 0.f);
    for (int j = rs + lane; j < re; j += 32) {
        int s = __ldg(&g_csr[j]);
        float4 as = ((const float4*)g_as1)[s];
        den.x += __expf(lrelu(as.x + ad4.x));
        den.y += __expf(lrelu(as.y + ad4.y));
        den.z += __expf(lrelu(as.z + ad4.z));
        den.w += __expf(lrelu(as.w + ad4.w));
    }
#pragma unroll
    for (int o = 16; o; o >>= 1) {
        den.x += __shfl_xor_sync(0xffffffffu, den.x, o);
        den.y += __shfl_xor_sync(0xffffffffu, den.y, o);
        den.z += __shfl_xor_sync(0xffffffffu, den.z, o);
        den.w += __shfl_xor_sync(0xffffffffu, den.w, o);
    }
    float4 as_self = ((const float4*)g_as1)[w];
    den.x += __expf(lrelu(as_self.x + ad4.x));
    den.y += __expf(lrelu(as_self.y + ad4.y));
    den.z += __expf(lrelu(as_self.z + ad4.z));
    den.w += __expf(lrelu(as_self.w + ad4.w));
    float denh = (h == 0) ? den.x : (h == 1) ? den.y : (h == 2) ? den.z : den.w;
    float invh = 1.f / denh;
    float ash = (h == 0) ? as_self.x : (h == 1) ? as_self.y : (h == 2) ? as_self.z : as_self.w;
    float wself = __expf(lrelu(ash + adh)) * invh;

    // pass 2: weighted gather
    float4 acc = make_float4(0.f, 0.f, 0.f, 0.f);
    for (int j = rs; j < re; j++) {
        int s = __ldg(&g_csr[j]);
        float a = g_as1[s * 4 + h];
        float ww = __expf(lrelu(a + adh)) * invh;
        float4 hv = *(const float4*)(g_h1 + (long long)s * 128 + lane * 4);
        acc.x += hv.x * ww;
        acc.y += hv.y * ww;
        acc.z += hv.z * ww;
        acc.w += hv.w * ww;
    }
    float4 hs = *(const float4*)(g_h1 + (long long)w * 128 + lane * 4);
    float4 bb = ((const float4*)b1)[lane];
    acc.x += hs.x * wself + bb.x;
    acc.y += hs.y * wself + bb.y;
    acc.z += hs.z * wself + bb.z;
    acc.w += hs.w * wself + bb.w;
    acc.x = acc.x > 0.f ? acc.x : (__expf(acc.x) - 1.f);
    acc.y = acc.y > 0.f ? acc.y : (__expf(acc.y) - 1.f);
    acc.z = acc.z > 0.f ? acc.z : (__expf(acc.z) - 1.f);
    acc.w = acc.w > 0.f ? acc.w : (__expf(acc.w) - 1.f);
    *(float4*)(g_out1 + (long long)w * 128 + lane * 4) = acc;
}

// ---------------- GEMM2: h2[N,32] = out1[N,128] @ W2[128,32] ----------------
__global__ void gemm2_kernel(const float* __restrict__ W, int n) {
    __shared__ float xs[64][68];
    __shared__ float ws[64][32];
    int tid = threadIdx.x;   // 128 threads
    int tx = tid & 7, ty = tid >> 3;
    int row0 = blockIdx.x * 64;
    float acc[4][4] = {};
    for (int kt = 0; kt < 2; kt++) {
        int kb = kt * 64;
        for (int i = tid; i < 4096; i += 128) {
            int r = i >> 6, k = i & 63;
            int gr = row0 + r;
            xs[k][r] = (gr < n) ? g_out1[(long long)gr * 128 + kb + k] : 0.f;
        }
        for (int i = tid; i < 2048; i += 128) {
            int k = i >> 5, c = i & 31;
            ws[k][c] = W[(kb + k) * 32 + c];
        }
        __syncthreads();
#pragma unroll 8
        for (int k = 0; k < 64; k++) {
            float4 a = *(const float4*)&xs[k][ty * 4];
            float4 b = *(const float4*)&ws[k][tx * 4];
            float ar[4] = {a.x, a.y, a.z, a.w};
            float br[4] = {b.x, b.y, b.z, b.w};
#pragma unroll
            for (int ii = 0; ii < 4; ii++)
#pragma unroll
                for (int jj = 0; jj < 4; jj++) acc[ii][jj] += ar[ii] * br[jj];
        }
        __syncthreads();
    }
#pragma unroll
    for (int ii = 0; ii < 4; ii++) {
        int gr = row0 + ty * 4 + ii;
        if (gr < n) {
            float4 v = make_float4(acc[ii][0], acc[ii][1], acc[ii][2], acc[ii][3]);
            *(float4*)&g_h2[gr * 32 + tx * 4] = v;
        }
    }
}

// ---------------- attention logits layer 2 ----------------
__global__ void att2_kernel(const float4* __restrict__ asr, const float4* __restrict__ adr, int n) {
    int i = blockIdx.x * blockDim.x + threadIdx.x;
    if (i >= n) return;
    const float4* hp = (const float4*)(g_h2 + i * 32);
    float s = 0.f, d = 0.f;
#pragma unroll
    for (int j = 0; j < 8; j++) {
        float4 v = hp[j];
        float4 a = asr[j];
        float4 b = adr[j];
        s += v.x * a.x + v.y * a.y + v.z * a.z + v.w * a.w;
        d += v.x * b.x + v.y * b.y + v.z * b.z + v.w * b.w;
    }
    g_as2[i] = s;
    g_ad2[i] = d;
}

// ---------------- layer2 aggregation + log_softmax: one warp per dst ----------------
__global__ void agg2_kernel(const float* __restrict__ b2, float* __restrict__ out, int n) {
    int w = (blockIdx.x * blockDim.x + threadIdx.x) >> 5;
    int lane = threadIdx.x & 31;
    if (w >= n) return;
    int rs = g_off[w], re = g_off[w + 1];
    float ad = g_ad2[w];

    // pass 1: denominator
    float den = 0.f;
    for (int j = rs + lane; j < re; j += 32) {
        int s = __ldg(&g_csr[j]);
        den += __expf(lrelu(g_as2[s] + ad));
    }
#pragma unroll
    for (int o = 16; o; o >>= 1) den += __shfl_xor_sync(0xffffffffu, den, o);
    float as_self = g_as2[w];
    den += __expf(lrelu(as_self + ad));
    float inv = 1.f / den;
    float wself = __expf(lrelu(as_self + ad)) * inv;

    // pass 2: weighted gather (lane = channel)
    float acc = 0.f;
    for (int j = rs; j < re; j++) {
        int s = __ldg(&g_csr[j]);
        float ww = __expf(lrelu(g_as2[s] + ad)) * inv;
        acc += g_h2[s * 32 + lane] * ww;
    }
    acc += g_h2[w * 32 + lane] * wself + b2[lane];

    // warp log_softmax over 32 channels
    float mx = acc;
#pragma unroll
    for (int o = 16; o; o >>= 1) mx = fmaxf(mx, __shfl_xor_sync(0xffffffffu, mx, o));
    float ex = __expf(acc - mx);
    float ssum = ex;
#pragma unroll
    for (int o = 16; o; o >>= 1) ssum += __shfl_xor_sync(0xffffffffu, ssum, o);
    out[(long long)w * 32 + lane] = acc - mx - logf(ssum);
}

extern "C" void kernel_launch(void* const* d_in, const int* in_sizes, int n_in,
                              void* d_out, int out_size) {
    const float* x     = (const float*)d_in[0];
    const int*   ei    = (const int*)d_in[1];
    const float* W1    = (const float*)d_in[2];
    const float* at_s1 = (const float*)d_in[3];
    const float* at_d1 = (const float*)d_in[4];
    const float* b1    = (const float*)d_in[5];
    const float* W2    = (const float*)d_in[6];
    const float* at_s2 = (const float*)d_in[7];
    const float* at_d2 = (const float*)d_in[8];
    const float* b2    = (const float*)d_in[9];
    float* out = (float*)d_out;

    int n = in_sizes[0] / 128;
    int e = in_sizes[1] / 2;
    const int* src = ei;
    const int* dst = ei + e;
    int nb = (n + 255) / 256;

    // CSR build (overlaps nothing; all default stream)
    zero_deg<<<nb, 256>>>(n);
    hist_kernel<<<(e + 255) / 256, 256>>>(dst, e);
    scan_block<<<nb, 256>>>(n);
    scan_top<<<1, 1024>>>(nb);
    scan_add<<<nb, 256>>>(n, e);
    fill_kernel<<<(e + 255) / 256, 256>>>(src, dst, e);

    dim3 g1((n + 63) / 64, 2);
    gemm1_kernel<<<g1, 256>>>(x, W1, n);
    att1_kernel<<<nb, 256>>>((const float4*)at_s1, (const float4*)at_d1, n);
    agg1_kernel<<<(n + 7) / 8, 256>>>(b1, n);

    gemm2_kernel<<<(n + 63) / 64, 128>>>(W2, n);
    att2_kernel<<<nb, 256>>>((const float4*)at_s2, (const float4*)at_d2, n);
    agg2_kernel<<<(n + 7) / 8, 256>>>(b2, out, n);
}